// round 8
// baseline (speedup 1.0000x reference)
// Model_star_44006234915144 — lambda * ||F^T F_star||_F^2
// Pass 1: fp32 -> bf16 pre-convert. Pass 2: bf16 mma.sync GEMM via cp.async.cg.
// CTA 128x128, 256 thr (4m x 2n warps), KC=64, 3-stage, 2 CTAs/SM.
// R8: per-warp kh phase rotation + B-fragment double buffering.
#include <cuda_runtime.h>
#include <cuda_bf16.h>
#include <cstdint>

#define DD 2048
#define NN 16384
#define TM 128
#define TN 128
#define KC 64
#define NCH (NN / KC)          // 256
#define STG 3
#define THREADS 256
#define ASTG (KC * TM * 2)     // 16384 B
#define BSTG (KC * TN * 2)     // 16384 B
#define STGSZ (ASTG + BSTG)    // 32768
#define SMEMSZ (STG * STGSZ)   // 98304 (x2 CTAs = 192KB/SM)
#define NCTAS ((DD / TN) * (DD / TM))   // 256

__device__ __align__(16) __nv_bfloat16 g_Abf[(size_t)NN * DD];  // F  in bf16
__device__ __align__(16) __nv_bfloat16 g_Bbf[(size_t)NN * DD];  // Fs in bf16
__device__ float g_partials[NCTAS];
__device__ unsigned int g_count;   // zero-init; self-resets each run

__device__ __forceinline__ uint32_t smem_u32(const void* p) {
    uint32_t a;
    asm("{ .reg .u64 t; cvta.to.shared.u64 t, %1; cvt.u32.u64 %0, t; }" : "=r"(a) : "l"(p));
    return a;
}
// reg = {hi: bf16(h), lo: bf16(l)}  -> memory order [l, h]
__device__ __forceinline__ uint32_t pack_bf16x2(float h, float l) {
    uint32_t r;
    asm("cvt.rn.bf16x2.f32 %0, %1, %2;" : "=r"(r) : "f"(h), "f"(l));
    return r;
}

#define CP_ASYNC16(dst, src)                                                       \
    asm volatile("cp.async.cg.shared.global [%0], [%1], 16;"                       \
                 :: "r"(dst), "l"(src) : "memory")
#define CP_COMMIT() asm volatile("cp.async.commit_group;" ::: "memory")
#define CP_WAIT1()  asm volatile("cp.async.wait_group 1;" ::: "memory")

#define LDSM_X4_T(r0, r1, r2, r3, ad)                                              \
    asm volatile("ldmatrix.sync.aligned.m8n8.x4.trans.shared.b16 {%0,%1,%2,%3}, [%4];" \
                 : "=r"(r0), "=r"(r1), "=r"(r2), "=r"(r3) : "r"(ad))

#define MMA16816(c, a, b0, b1)                                                     \
    asm volatile("mma.sync.aligned.m16n8k16.row.col.f32.bf16.bf16.f32 "            \
                 "{%0,%1,%2,%3}, {%4,%5,%6,%7}, {%8,%9}, {%0,%1,%2,%3};"           \
                 : "+f"((c)[0]), "+f"((c)[1]), "+f"((c)[2]), "+f"((c)[3])          \
                 : "r"((a)[0]), "r"((a)[1]), "r"((a)[2]), "r"((a)[3]),             \
                   "r"(b0), "r"(b1))

// ---------------- pass 1: fp32 -> bf16 ----------------
__global__ void __launch_bounds__(256)
cvt_kernel(const float* __restrict__ F, const float* __restrict__ Fs) {
    const size_t NF4 = (size_t)NN * DD / 4;
    const float4* src = (blockIdx.y == 0) ? (const float4*)F : (const float4*)Fs;
    uint2* dst = (uint2*)((blockIdx.y == 0) ? g_Abf : g_Bbf);
    const size_t stride = (size_t)gridDim.x * 256;
    for (size_t i = (size_t)blockIdx.x * 256 + threadIdx.x; i < NF4; i += stride) {
        float4 v = src[i];
        uint2 o;
        o.x = pack_bf16x2(v.y, v.x);
        o.y = pack_bf16x2(v.w, v.z);
        dst[i] = o;
    }
}

// ---------------- pass 2: GEMM + square-sum ----------------
__global__ void __launch_bounds__(THREADS, 2)
gram_kernel(const float* __restrict__ lam, float* __restrict__ out) {
    extern __shared__ char smem[];
    const uint32_t sb = smem_u32(smem);
    const int t = threadIdx.x;
    const int L = t & 31;
    const int w = t >> 5;

    const int d0 = blockIdx.y * TM;
    const int e0 = blockIdx.x * TN;

    // ---- cp.async mapping: thread owns (k0 + j*16, c16) 16B slots, j=0..3 ----
    const int k0  = t >> 4;         // 0..15
    const int c16 = t & 15;         // 0..15 (16B unit within 256B row)
    const uint32_t cpsw  = (uint32_t)(k0 & 7) << 4;
    const uint32_t cpoff = ((uint32_t)c16 * 16u) ^ cpsw;
    const __nv_bfloat16* pA = g_Abf + (size_t)k0 * DD + d0 + c16 * 8;
    const __nv_bfloat16* pB = g_Bbf + (size_t)k0 * DD + e0 + c16 * 8;
    const size_t stepj = (size_t)16 * DD;   // 16 k-rows
    const size_t stepc = (size_t)KC * DD;   // one chunk

    // ---- mma fragment smem addressing (proven geometry) ----
    const int wm = w & 3;           // 4 warps along m (32 rows each)
    const int wn = w >> 2;          // 2 warps along n (64 cols each)
    const uint32_t kL     = (uint32_t)((L & 7) + ((L & 16) >> 1));   // 0..15
    const uint32_t rowOff = kL * 256u;
    const uint32_t swz    = (uint32_t)(L & 7) << 4;
    const uint32_t aCol   = (uint32_t)((wm * 32 + (L & 8)) * 2);
    const uint32_t bCol   = (uint32_t)((wn * 64 + (L & 8)) * 2);

    float acc[2][8][4];
    #pragma unroll
    for (int i = 0; i < 2; i++)
        #pragma unroll
        for (int j = 0; j < 8; j++)
            #pragma unroll
            for (int q = 0; q < 4; q++) acc[i][j][q] = 0.0f;

    // issue one stage's copies (8 x 16B per thread)
    #define ISSUE(c) do {                                                          \
        uint32_t stg = sb + (uint32_t)((c) % STG) * STGSZ;                         \
        const __nv_bfloat16* sa = pA + (size_t)(c) * stepc;                        \
        const __nv_bfloat16* sbp = pB + (size_t)(c) * stepc;                       \
        _Pragma("unroll")                                                          \
        for (int j = 0; j < 4; j++) {                                              \
            uint32_t d = stg + (uint32_t)(k0 + j * 16) * 256u + cpoff;             \
            CP_ASYNC16(d, sa + (size_t)j * stepj);                                 \
        }                                                                          \
        _Pragma("unroll")                                                          \
        for (int j = 0; j < 4; j++) {                                              \
            uint32_t d = stg + ASTG + (uint32_t)(k0 + j * 16) * 256u + cpoff;      \
            CP_ASYNC16(d, sbp + (size_t)j * stepj);                                \
        }                                                                          \
    } while (0)

    ISSUE(0); CP_COMMIT();
    ISSUE(1); CP_COMMIT();

    #pragma unroll 1
    for (int it = 0; it < NCH; ++it) {
        CP_WAIT1();
        __syncthreads();
        if (it + 2 < NCH) ISSUE(it + 2);
        CP_COMMIT();   // empty tail groups keep wait_group semantics uniform

        const uint32_t sA = sb + (uint32_t)(it % STG) * STGSZ;
        const uint32_t sB = sA + ASTG;

        #pragma unroll
        for (int khi = 0; khi < 4; khi++) {
            const int kh = (khi + w) & 3;           // per-warp phase rotation
            const uint32_t aBase = sA + (uint32_t)kh * 4096u + rowOff;
            const uint32_t bBase = sB + (uint32_t)kh * 4096u + rowOff;

            uint32_t a[2][4];
            #pragma unroll
            for (int mt = 0; mt < 2; mt++) {
                uint32_t ad = aBase + ((aCol + (uint32_t)mt * 32u) ^ swz);
                LDSM_X4_T(a[mt][0], a[mt][1], a[mt][2], a[mt][3], ad);
            }

            uint32_t bc[4], bn[4];
            LDSM_X4_T(bc[0], bc[1], bc[2], bc[3], bBase + (bCol ^ swz));
            #pragma unroll
            for (int nt = 0; nt < 4; nt++) {
                if (nt < 3) {
                    uint32_t bd = bBase + ((bCol + (uint32_t)(nt + 1) * 32u) ^ swz);
                    LDSM_X4_T(bn[0], bn[1], bn[2], bn[3], bd);
                }
                #pragma unroll
                for (int mt = 0; mt < 2; mt++) {
                    MMA16816(acc[mt][nt * 2 + 0], a[mt], bc[0], bc[2]);
                    MMA16816(acc[mt][nt * 2 + 1], a[mt], bc[1], bc[3]);
                }
                if (nt < 3) {
                    bc[0] = bn[0]; bc[1] = bn[1]; bc[2] = bn[2]; bc[3] = bn[3];
                }
            }
        }
        __syncthreads();   // all warps done reading stage it before it is rewritten
    }

    // ---------------- square-sum epilogue (deterministic) ----------------
    float s = 0.0f;
    #pragma unroll
    for (int i = 0; i < 2; i++)
        #pragma unroll
        for (int j = 0; j < 8; j++)
            #pragma unroll
            for (int q = 0; q < 4; q++) {
                float v = acc[i][j][q];
                s += v * v;
            }
    #pragma unroll
    for (int o = 16; o > 0; o >>= 1) s += __shfl_xor_sync(0xFFFFFFFFu, s, o);

    __syncthreads();                       // stage buffers dead; reuse for reduction
    float* red = (float*)smem;
    if (L == 0) red[w] = s;
    __syncthreads();

    // ---- last-CTA final reduction (deterministic order, graph-replay safe) ----
    if (t == 0) {
        float tot = 0.0f;
        #pragma unroll
        for (int i = 0; i < 8; i++) tot += red[i];
        g_partials[blockIdx.y * (DD / TN) + blockIdx.x] = tot;
        __threadfence();
        unsigned int old = atomicAdd(&g_count, 1u);
        if (old == NCTAS - 1) {
            const float4* gp = (const float4*)g_partials;
            float total = 0.0f;
            #pragma unroll 8
            for (int i = 0; i < NCTAS / 4; i++) {
                float4 v = gp[i];
                total += (v.x + v.y) + (v.z + v.w);
            }
            out[0] = lam[0] * total;
            __threadfence();
            g_count = 0;                   // reset for next graph replay
        }
    }
}

extern "C" void kernel_launch(void* const* d_in, const int* in_sizes, int n_in,
                              void* d_out, int out_size) {
    const float* F   = (const float*)d_in[0];
    const float* Fst = (const float*)d_in[1];
    const float* lam = (const float*)d_in[2];
    (void)in_sizes; (void)n_in; (void)out_size;

    cudaFuncSetAttribute(gram_kernel, cudaFuncAttributeMaxDynamicSharedMemorySize, SMEMSZ);

    cvt_kernel<<<dim3(2048, 2), 256>>>(F, Fst);
    dim3 grid(DD / TN, DD / TM);   // (16, 16) = 256 CTAs, 2/SM
    gram_kernel<<<grid, THREADS, SMEMSZ>>>(lam, (float*)d_out);
}

// round 9
// speedup vs baseline: 1.0927x; 1.0927x over previous
// Model_star_44006234915144 — lambda * ||F^T F_star||_F^2
// Pass 1: fp32 -> bf16 pre-convert. Pass 2: bf16 mma.sync GEMM via cp.async.cg.
// CTA 128x128, 256 thr (4m x 2n warps), KC=64, 3-stage, 2 CTAs/SM.
// R9: revert R8 inner loop to R7; single __syncthreads per chunk (stage math
// proves the bottom barrier redundant); incremental stage offsets.
#include <cuda_runtime.h>
#include <cuda_bf16.h>
#include <cstdint>

#define DD 2048
#define NN 16384
#define TM 128
#define TN 128
#define KC 64
#define NCH (NN / KC)          // 256
#define STG 3
#define THREADS 256
#define ASTG (KC * TM * 2)     // 16384 B
#define BSTG (KC * TN * 2)     // 16384 B
#define STGSZ (ASTG + BSTG)    // 32768
#define SMEMSZ (STG * STGSZ)   // 98304 (x2 CTAs = 192KB/SM)
#define NCTAS ((DD / TN) * (DD / TM))   // 256

__device__ __align__(16) __nv_bfloat16 g_Abf[(size_t)NN * DD];  // F  in bf16
__device__ __align__(16) __nv_bfloat16 g_Bbf[(size_t)NN * DD];  // Fs in bf16
__device__ float g_partials[NCTAS];
__device__ unsigned int g_count;   // zero-init; self-resets each run

__device__ __forceinline__ uint32_t smem_u32(const void* p) {
    uint32_t a;
    asm("{ .reg .u64 t; cvta.to.shared.u64 t, %1; cvt.u32.u64 %0, t; }" : "=r"(a) : "l"(p));
    return a;
}
// reg = {hi: bf16(h), lo: bf16(l)}  -> memory order [l, h]
__device__ __forceinline__ uint32_t pack_bf16x2(float h, float l) {
    uint32_t r;
    asm("cvt.rn.bf16x2.f32 %0, %1, %2;" : "=r"(r) : "f"(h), "f"(l));
    return r;
}

#define CP_ASYNC16(dst, src)                                                       \
    asm volatile("cp.async.cg.shared.global [%0], [%1], 16;"                       \
                 :: "r"(dst), "l"(src) : "memory")
#define CP_COMMIT() asm volatile("cp.async.commit_group;" ::: "memory")
#define CP_WAIT1()  asm volatile("cp.async.wait_group 1;" ::: "memory")

#define LDSM_X4_T(r0, r1, r2, r3, ad)                                              \
    asm volatile("ldmatrix.sync.aligned.m8n8.x4.trans.shared.b16 {%0,%1,%2,%3}, [%4];" \
                 : "=r"(r0), "=r"(r1), "=r"(r2), "=r"(r3) : "r"(ad))

#define MMA16816(c, a, b0, b1)                                                     \
    asm volatile("mma.sync.aligned.m16n8k16.row.col.f32.bf16.bf16.f32 "            \
                 "{%0,%1,%2,%3}, {%4,%5,%6,%7}, {%8,%9}, {%0,%1,%2,%3};"           \
                 : "+f"((c)[0]), "+f"((c)[1]), "+f"((c)[2]), "+f"((c)[3])          \
                 : "r"((a)[0]), "r"((a)[1]), "r"((a)[2]), "r"((a)[3]),             \
                   "r"(b0), "r"(b1))

// ---------------- pass 1: fp32 -> bf16 ----------------
__global__ void __launch_bounds__(256)
cvt_kernel(const float* __restrict__ F, const float* __restrict__ Fs) {
    const size_t NF4 = (size_t)NN * DD / 4;
    const float4* src = (blockIdx.y == 0) ? (const float4*)F : (const float4*)Fs;
    uint2* dst = (uint2*)((blockIdx.y == 0) ? g_Abf : g_Bbf);
    const size_t stride = (size_t)gridDim.x * 256;
    for (size_t i = (size_t)blockIdx.x * 256 + threadIdx.x; i < NF4; i += stride) {
        float4 v = src[i];
        uint2 o;
        o.x = pack_bf16x2(v.y, v.x);
        o.y = pack_bf16x2(v.w, v.z);
        dst[i] = o;
    }
}

// ---------------- pass 2: GEMM + square-sum ----------------
__global__ void __launch_bounds__(THREADS, 2)
gram_kernel(const float* __restrict__ lam, float* __restrict__ out) {
    extern __shared__ char smem[];
    const uint32_t sb = smem_u32(smem);
    const int t = threadIdx.x;
    const int L = t & 31;
    const int w = t >> 5;

    const int d0 = blockIdx.y * TM;
    const int e0 = blockIdx.x * TN;

    // ---- cp.async mapping: thread owns (k0 + j*16, c16) 16B slots, j=0..3 ----
    const int k0  = t >> 4;         // 0..15
    const int c16 = t & 15;         // 0..15 (16B unit within 256B row)
    const uint32_t cpsw  = (uint32_t)(k0 & 7) << 4;
    const uint32_t cpoff = ((uint32_t)c16 * 16u) ^ cpsw;
    const __nv_bfloat16* pA = g_Abf + (size_t)k0 * DD + d0 + c16 * 8;
    const __nv_bfloat16* pB = g_Bbf + (size_t)k0 * DD + e0 + c16 * 8;
    const size_t stepj = (size_t)16 * DD;   // 16 k-rows
    const size_t stepc = (size_t)KC * DD;   // one chunk

    // ---- mma fragment smem addressing (proven R7 geometry) ----
    const int wm = w & 3;           // 4 warps along m (32 rows each)
    const int wn = w >> 2;          // 2 warps along n (64 cols each)
    const uint32_t kL     = (uint32_t)((L & 7) + ((L & 16) >> 1));   // 0..15
    const uint32_t rowOff = kL * 256u;
    const uint32_t swz    = (uint32_t)(L & 7) << 4;
    const uint32_t aCol   = (uint32_t)((wm * 32 + (L & 8)) * 2);
    const uint32_t bCol   = (uint32_t)((wn * 64 + (L & 8)) * 2);

    float acc[2][8][4];
    #pragma unroll
    for (int i = 0; i < 2; i++)
        #pragma unroll
        for (int j = 0; j < 8; j++)
            #pragma unroll
            for (int q = 0; q < 4; q++) acc[i][j][q] = 0.0f;

    // issue one stage's copies (8 x 16B per thread) into stage offset so
    #define ISSUE_AT(c, so) do {                                                   \
        uint32_t stg = sb + (so);                                                  \
        const __nv_bfloat16* sa = pA + (size_t)(c) * stepc;                        \
        const __nv_bfloat16* sbp = pB + (size_t)(c) * stepc;                       \
        _Pragma("unroll")                                                          \
        for (int j = 0; j < 4; j++) {                                              \
            uint32_t d = stg + (uint32_t)(k0 + j * 16) * 256u + cpoff;             \
            CP_ASYNC16(d, sa + (size_t)j * stepj);                                 \
        }                                                                          \
        _Pragma("unroll")                                                          \
        for (int j = 0; j < 4; j++) {                                              \
            uint32_t d = stg + ASTG + (uint32_t)(k0 + j * 16) * 256u + cpoff;      \
            CP_ASYNC16(d, sbp + (size_t)j * stepj);                                \
        }                                                                          \
    } while (0)

    ISSUE_AT(0, 0); CP_COMMIT();
    ISSUE_AT(1, STGSZ); CP_COMMIT();

    uint32_t soRead = 0;            // stage offset of chunk it
    uint32_t soWrite = 2 * STGSZ;   // stage offset of chunk it+2

    #pragma unroll 1
    for (int it = 0; it < NCH; ++it) {
        CP_WAIT1();
        __syncthreads();
        // Safe: stage soWrite == stage of chunk it-1; by program order every
        // warp finished reading chunk it-1 before arriving at the sync above.
        if (it + 2 < NCH) ISSUE_AT(it + 2, soWrite);
        CP_COMMIT();   // empty tail groups keep wait_group semantics uniform

        const uint32_t sA = sb + soRead;
        const uint32_t sB = sA + ASTG;

        #pragma unroll
        for (int kh = 0; kh < 4; kh++) {
            uint32_t a[2][4];
            #pragma unroll
            for (int mt = 0; mt < 2; mt++) {
                uint32_t ad = sA + (uint32_t)kh * 4096u + rowOff
                            + ((aCol + (uint32_t)mt * 32u) ^ swz);
                LDSM_X4_T(a[mt][0], a[mt][1], a[mt][2], a[mt][3], ad);
            }
            #pragma unroll
            for (int nt = 0; nt < 4; nt++) {
                uint32_t b0, b1, b2, b3;
                uint32_t bd = sB + (uint32_t)kh * 4096u + rowOff
                            + ((bCol + (uint32_t)nt * 32u) ^ swz);
                LDSM_X4_T(b0, b1, b2, b3, bd);
                #pragma unroll
                for (int mt = 0; mt < 2; mt++) {
                    MMA16816(acc[mt][nt * 2 + 0], a[mt], b0, b2);
                    MMA16816(acc[mt][nt * 2 + 1], a[mt], b1, b3);
                }
            }
        }

        soRead  += STGSZ; if (soRead  == STG * STGSZ) soRead  = 0;
        soWrite += STGSZ; if (soWrite == STG * STGSZ) soWrite = 0;
    }

    // ---------------- square-sum epilogue (deterministic) ----------------
    float s = 0.0f;
    #pragma unroll
    for (int i = 0; i < 2; i++)
        #pragma unroll
        for (int j = 0; j < 8; j++)
            #pragma unroll
            for (int q = 0; q < 4; q++) {
                float v = acc[i][j][q];
                s += v * v;
            }
    #pragma unroll
    for (int o = 16; o > 0; o >>= 1) s += __shfl_xor_sync(0xFFFFFFFFu, s, o);

    __syncthreads();                       // stage buffers dead; reuse for reduction
    float* red = (float*)smem;
    if (L == 0) red[w] = s;
    __syncthreads();

    // ---- last-CTA final reduction (deterministic order, graph-replay safe) ----
    if (t == 0) {
        float tot = 0.0f;
        #pragma unroll
        for (int i = 0; i < 8; i++) tot += red[i];
        g_partials[blockIdx.y * (DD / TN) + blockIdx.x] = tot;
        __threadfence();
        unsigned int old = atomicAdd(&g_count, 1u);
        if (old == NCTAS - 1) {
            const float4* gp = (const float4*)g_partials;
            float total = 0.0f;
            #pragma unroll 8
            for (int i = 0; i < NCTAS / 4; i++) {
                float4 v = gp[i];
                total += (v.x + v.y) + (v.z + v.w);
            }
            out[0] = lam[0] * total;
            __threadfence();
            g_count = 0;                   // reset for next graph replay
        }
    }
}

extern "C" void kernel_launch(void* const* d_in, const int* in_sizes, int n_in,
                              void* d_out, int out_size) {
    const float* F   = (const float*)d_in[0];
    const float* Fst = (const float*)d_in[1];
    const float* lam = (const float*)d_in[2];
    (void)in_sizes; (void)n_in; (void)out_size;

    cudaFuncSetAttribute(gram_kernel, cudaFuncAttributeMaxDynamicSharedMemorySize, SMEMSZ);

    cvt_kernel<<<dim3(2048, 2), 256>>>(F, Fst);
    dim3 grid(DD / TN, DD / TM);   // (16, 16) = 256 CTAs, 2/SM
    gram_kernel<<<grid, THREADS, SMEMSZ>>>(lam, (float*)d_out);
}